// round 3
// baseline (speedup 1.0000x reference)
#include <cuda_runtime.h>
#include <math.h>

#define NBLOCKS  2048
#define NTHREADS 256

__device__ float g_partials[NBLOCKS];

__global__ void __launch_bounds__(NTHREADS, 1)
sq_partial_kernel(const float4* __restrict__ o,
                  const float4* __restrict__ x,
                  long n4)
{
    float acc = 0.0f;
    const long stride  = (long)gridDim.x * (long)blockDim.x;   // 524288
    const long stride2 = 2 * stride;
    long i = (long)blockIdx.x * blockDim.x + threadIdx.x;

    // Main loop: 2x unrolled, 4 independent 16B loads front-batched per iter
    // (raises MLP_eff, hides DRAM latency at this occupancy).
    long end2 = n4 - stride;           // safe bound for the i+stride access
    if (end2 < 0) end2 = 0;            // tiny-input guard
    for (; i < end2; i += stride2) {
        float4 a0 = o[i];
        float4 b0 = x[i];
        float4 a1 = o[i + stride];
        float4 b1 = x[i + stride];

        float d0 = a0.x - b0.x, d1 = a0.y - b0.y;
        float d2 = a0.z - b0.z, d3 = a0.w - b0.w;
        acc = fmaf(d0, d0, acc);
        acc = fmaf(d1, d1, acc);
        acc = fmaf(d2, d2, acc);
        acc = fmaf(d3, d3, acc);

        float e0 = a1.x - b1.x, e1 = a1.y - b1.y;
        float e2 = a1.z - b1.z, e3 = a1.w - b1.w;
        acc = fmaf(e0, e0, acc);
        acc = fmaf(e1, e1, acc);
        acc = fmaf(e2, e2, acc);
        acc = fmaf(e3, e3, acc);
    }
    // Remainder (non-divisible cases and the final trailing stride chunk).
    for (; i < n4; i += stride) {
        float4 a = o[i];
        float4 b = x[i];
        float d0 = a.x - b.x, d1 = a.y - b.y;
        float d2 = a.z - b.z, d3 = a.w - b.w;
        acc = fmaf(d0, d0, acc);
        acc = fmaf(d1, d1, acc);
        acc = fmaf(d2, d2, acc);
        acc = fmaf(d3, d3, acc);
    }

    // Warp reduce
    #pragma unroll
    for (int off = 16; off > 0; off >>= 1)
        acc += __shfl_xor_sync(0xffffffffu, acc, off);

    __shared__ float s_warp[NTHREADS / 32];
    if ((threadIdx.x & 31) == 0)
        s_warp[threadIdx.x >> 5] = acc;
    __syncthreads();

    if (threadIdx.x < 32) {
        float v = (threadIdx.x < NTHREADS / 32) ? s_warp[threadIdx.x] : 0.0f;
        #pragma unroll
        for (int off = 4; off > 0; off >>= 1)
            v += __shfl_xor_sync(0xffffffffu, v, off);
        if (threadIdx.x == 0)
            g_partials[blockIdx.x] = v;
    }
}

__global__ void __launch_bounds__(1024, 1)
finalize_kernel(const float* __restrict__ noise_p,
                float* __restrict__ out,
                long n, long d)
{
    const int tid = threadIdx.x;

    // Accumulate the 2048 block partials in double to kill ordering error.
    double acc = 0.0;
    for (int i = tid; i < NBLOCKS; i += blockDim.x)
        acc += (double)g_partials[i];

    #pragma unroll
    for (int off = 16; off > 0; off >>= 1)
        acc += __shfl_xor_sync(0xffffffffu, acc, off);

    __shared__ double s_warp[32];
    if ((tid & 31) == 0)
        s_warp[tid >> 5] = acc;
    __syncthreads();

    if (tid == 0) {
        double total = 0.0;
        #pragma unroll
        for (int w = 0; w < 32; w++)
            total += s_warp[w];

        float sq     = (float)total;
        float noise  = *noise_p;
        float log2pi = logf(2.0f * 3.14159265358979323846f);
        float nd     = (float)(n * d);           // 67108864, exact in fp32
        float result = -0.5f * nd * log2pi
                       - 0.5f * (float)n * noise
                       - 0.5f * expf(-2.0f * noise) * sq;
        out[0] = result;
    }
}

extern "C" void kernel_launch(void* const* d_in, const int* in_sizes, int n_in,
                              void* d_out, int out_size)
{
    const float* o       = (const float*)d_in[0];
    const float* x       = (const float*)d_in[1];
    const float* noise_p = (const float*)d_in[2];
    float* out           = (float*)d_out;

    const long n_elem = (long)in_sizes[0];     // 67108864
    const long n4     = n_elem / 4;            // 16777216 float4s
    const long n      = 65536;
    const long d      = n_elem / n;            // 1024

    sq_partial_kernel<<<NBLOCKS, NTHREADS>>>((const float4*)o, (const float4*)x, n4);
    finalize_kernel<<<1, 1024>>>(noise_p, out, n, d);
}

// round 6
// speedup vs baseline: 1.0530x; 1.0530x over previous
#include <cuda_runtime.h>
#include <math.h>

#define NBLOCKS  2048
#define NTHREADS 256

__device__ float g_partials[NBLOCKS];
__device__ unsigned int g_count = 0;   // reset to 0 by the last block every run

__global__ void __launch_bounds__(NTHREADS, 1)
lik_fused_kernel(const float4* __restrict__ o,
                 const float4* __restrict__ x,
                 const float* __restrict__ noise_p,
                 float* __restrict__ out,
                 long n4, long n, long d)
{
    float acc = 0.0f;
    const long stride  = (long)gridDim.x * (long)blockDim.x;   // 524288
    const long stride2 = 2 * stride;
    long i = (long)blockIdx.x * blockDim.x + threadIdx.x;

    // Main loop: 2x unrolled, 4 independent 16B loads front-batched per iter.
    long end2 = n4 - stride;
    if (end2 < 0) end2 = 0;
    for (; i < end2; i += stride2) {
        float4 a0 = o[i];
        float4 b0 = x[i];
        float4 a1 = o[i + stride];
        float4 b1 = x[i + stride];

        float d0 = a0.x - b0.x, d1 = a0.y - b0.y;
        float d2 = a0.z - b0.z, d3 = a0.w - b0.w;
        acc = fmaf(d0, d0, acc);
        acc = fmaf(d1, d1, acc);
        acc = fmaf(d2, d2, acc);
        acc = fmaf(d3, d3, acc);

        float e0 = a1.x - b1.x, e1 = a1.y - b1.y;
        float e2 = a1.z - b1.z, e3 = a1.w - b1.w;
        acc = fmaf(e0, e0, acc);
        acc = fmaf(e1, e1, acc);
        acc = fmaf(e2, e2, acc);
        acc = fmaf(e3, e3, acc);
    }
    for (; i < n4; i += stride) {
        float4 a = o[i];
        float4 b = x[i];
        float d0 = a.x - b.x, d1 = a.y - b.y;
        float d2 = a.z - b.z, d3 = a.w - b.w;
        acc = fmaf(d0, d0, acc);
        acc = fmaf(d1, d1, acc);
        acc = fmaf(d2, d2, acc);
        acc = fmaf(d3, d3, acc);
    }

    // ---- Block reduce (fp32) ----
    #pragma unroll
    for (int off = 16; off > 0; off >>= 1)
        acc += __shfl_xor_sync(0xffffffffu, acc, off);

    __shared__ float s_warp[NTHREADS / 32];
    if ((threadIdx.x & 31) == 0)
        s_warp[threadIdx.x >> 5] = acc;
    __syncthreads();

    if (threadIdx.x < 32) {
        float v = (threadIdx.x < NTHREADS / 32) ? s_warp[threadIdx.x] : 0.0f;
        #pragma unroll
        for (int off = 4; off > 0; off >>= 1)
            v += __shfl_xor_sync(0xffffffffu, v, off);
        if (threadIdx.x == 0)
            g_partials[blockIdx.x] = v;
    }

    // ---- Last-block-done: fused finalize ----
    __shared__ bool s_is_last;
    __threadfence();                          // make g_partials[blockIdx.x] visible
    if (threadIdx.x == 0) {
        unsigned int prev = atomicAdd(&g_count, 1u);
        s_is_last = (prev == gridDim.x - 1);
    }
    __syncthreads();

    if (s_is_last) {
        // Deterministic, index-ordered reduce of 2048 partials in double.
        const int tid = threadIdx.x;
        double dacc = 0.0;
        #pragma unroll
        for (int k = tid; k < NBLOCKS; k += NTHREADS)
            dacc += (double)g_partials[k];

        #pragma unroll
        for (int off = 16; off > 0; off >>= 1)
            dacc += __shfl_xor_sync(0xffffffffu, dacc, off);

        __shared__ double s_dw[NTHREADS / 32];
        if ((tid & 31) == 0)
            s_dw[tid >> 5] = dacc;
        __syncthreads();

        if (tid == 0) {
            double total = 0.0;
            #pragma unroll
            for (int w = 0; w < NTHREADS / 32; w++)
                total += s_dw[w];

            float sq     = (float)total;
            float noise  = *noise_p;
            float log2pi = logf(2.0f * 3.14159265358979323846f);
            float nd     = (float)(n * d);      // 67108864, exact in fp32
            float result = -0.5f * nd * log2pi
                           - 0.5f * (float)n * noise
                           - 0.5f * expf(-2.0f * noise) * sq;
            out[0]  = result;
            g_count = 0;                        // reset for the next (graph) replay
        }
    }
}

extern "C" void kernel_launch(void* const* d_in, const int* in_sizes, int n_in,
                              void* d_out, int out_size)
{
    const float* o       = (const float*)d_in[0];
    const float* x       = (const float*)d_in[1];
    const float* noise_p = (const float*)d_in[2];
    float* out           = (float*)d_out;

    const long n_elem = (long)in_sizes[0];     // 67108864
    const long n4     = n_elem / 4;            // 16777216 float4s
    const long n      = 65536;
    const long d      = n_elem / n;            // 1024

    lik_fused_kernel<<<NBLOCKS, NTHREADS>>>((const float4*)o, (const float4*)x,
                                            noise_p, out, n4, n, d);
}